// round 15
// baseline (speedup 1.0000x reference)
#include <cuda_runtime.h>
#include <cuda_fp16.h>
#include <cstdint>

// ---------------- problem constants ----------------
#define NUM_CTAS 147
#define NTHREADS 512
#define NWARPS   16
#define HDIM     2048
#define EDIM     1024
#define UPC      14          // units per CTA (146*14 + 4 = 2048)
#define UH       12          // units handled by HMMA (48 rows = 3 m16 tiles)
#define MAXT     2048
#define WSTRIDE  4096        // bytes per smem weight row (2048 fp16)
#define PSTRIDE  68          // part[] strip stride in floats (rows 0..55 used)
#define ACACHE   10          // HMMA iters with register-cached A fragments (R12 optimum)

// smem layout (bytes)
#define OFF_W     0
#define OFF_HS2   (48 * WSTRIDE)             // half h copy (4KB)
#define OFF_WO2   (OFF_HS2 + 4096)           // packed fp16 W_out (8KB)
#define OFF_WPART (OFF_WO2 + 8192)           // per-thread wout partials (4KB)
#define OFF_PART  (OFF_WPART + 4096)         // 4 strips x 68 floats
#define OFF_A0    (OFF_PART + 4 * PSTRIDE * 4)
#define OFF_A1    (OFF_A0 + 256)
#define OFF_DD    (OFF_A1 + 256)
#define OFF_VW    (OFF_DD + 256)
#define SMEM_TOTAL (OFF_VW + 64)

// ---------------- device globals ----------------
__device__ __half    g_h2[2][HDIM];         // double-buffered hidden state (fp16)
__device__ unsigned  g_bar_cnt;             // central barrier (cnt returns to 0)
__device__ unsigned  g_bar_gen;             // monotonically increasing gen

// ---------------- helpers ----------------
__device__ __forceinline__ unsigned ld_acq_u32(const unsigned* p) {
    unsigned v; asm volatile("ld.acquire.gpu.u32 %0, [%1];" : "=r"(v) : "l"(p)); return v;
}
__device__ __forceinline__ void stcg_u16(__half* p, __half v) {
    unsigned short b = __half_as_ushort(v);
    asm volatile("st.global.cg.u16 [%0], %1;" :: "l"(p), "h"(b) : "memory");
}
__device__ __forceinline__ uint2 ldcg_u2(const uint2* p) {
    uint2 v;
    asm volatile("ld.global.cg.v2.u32 {%0,%1}, [%2];"
                 : "=r"(v.x), "=r"(v.y) : "l"(p));
    return v;
}
__device__ __forceinline__ float sigf(float x) { return 1.0f / (1.0f + __expf(-x)); }
__device__ __forceinline__ float tanhfast(float x) {
    return 1.0f - 2.0f / (__expf(2.0f * x) + 1.0f);
}

// dot of 16 fp16 pairs (weights w0:w1, h h0:h1), fp32 accumulate
__device__ __forceinline__ float dot16(uint4 w0, uint4 w1, uint4 h0, uint4 h1) {
    float a0 = 0.f, a1 = 0.f, a2 = 0.f, a3 = 0.f;
    const __half2* wp0 = (const __half2*)&w0;
    const __half2* wp1 = (const __half2*)&w1;
    const __half2* hp0 = (const __half2*)&h0;
    const __half2* hp1 = (const __half2*)&h1;
    #pragma unroll
    for (int i = 0; i < 4; i++) {
        float2 f = __half22float2(wp0[i]);
        float2 g = __half22float2(hp0[i]);
        a0 = fmaf(f.x, g.x, a0); a1 = fmaf(f.y, g.y, a1);
        float2 f2 = __half22float2(wp1[i]);
        float2 g2 = __half22float2(hp1[i]);
        a2 = fmaf(f2.x, g2.x, a2); a3 = fmaf(f2.y, g2.y, a3);
    }
    return (a0 + a1) + (a2 + a3);
}

// Barrier with per-warp wake: entry bar orders smem/h work; tid0 arrives;
// every warp's lane 0 polls gen >= expect, then syncwarp (no trailing bar).
__device__ __forceinline__ void grid_barrier_exp(int lane, unsigned expect) {
    __syncthreads();
    if (lane == 0) {
        if (threadIdx.x == 0) {
            __threadfence();
            if (atomicAdd(&g_bar_cnt, 1u) == NUM_CTAS - 1u) {
                g_bar_cnt = 0u;
                __threadfence();
                atomicAdd(&g_bar_gen, 1u);
            }
        }
        while ((int)(ld_acq_u32(&g_bar_gen) - expect) < 0) { }
    }
    __syncwarp();
}

// ---------------- kernel ----------------
__global__ void __launch_bounds__(NTHREADS, 1)
lstm_decoder_kernel(const float* __restrict__ h0, const float* __restrict__ c0,
                    const float* __restrict__ gtruth, const int* __restrict__ use_gt,
                    const float* __restrict__ W_emb, const float* __restrict__ b_emb,
                    const float* __restrict__ W_ih, const float* __restrict__ b_ih,
                    const float* __restrict__ W_hh, const float* __restrict__ b_hh,
                    const float* __restrict__ W_out, const float* __restrict__ b_out,
                    const int* __restrict__ out_len_ptr, float* __restrict__ out)
{
    const int cta  = blockIdx.x;
    const int tid  = threadIdx.x;
    const int lane = tid & 31;
    const int warp = tid >> 5;

    int nu = HDIM - cta * UPC;                 // 14 (ctas 0..145), 4 (cta 146)
    nu = (nu < 0) ? 0 : (nu > UPC ? UPC : nu);
    const int uh = (nu < UH) ? nu : UH;
    const int nrows = 4 * nu;

    int T = MAXT;
    if (out_len_ptr) { int tt = *out_len_ptr; if (tt > 0 && tt <= MAXT) T = tt; }

    extern __shared__ __align__(16) char sm[];
    char*   w_s   = sm + OFF_W;
    char*   h_s2  = sm + OFF_HS2;
    uint4*  wo2_s = (uint4*)(sm + OFF_WO2);
    float2* wpart = (float2*)(sm + OFF_WPART);
    float*  part  = (float*)(sm + OFF_PART);     // [4][PSTRIDE], rows 0..55
    float*  A0    = (float*)(sm + OFF_A0);
    float*  A1    = (float*)(sm + OFF_A1);
    float*  DD    = (float*)(sm + OFF_DD);
    float*  VW    = (float*)(sm + OFF_VW);
    const uint32_t smem_u32 = (uint32_t)__cvta_generic_to_shared(sm);

    // base generation: read by ALL threads before the first barrier's entry sync.
    // First flip can only occur after all 147 tid0s arrive, i.e. after every
    // thread everywhere has read this — so gbase is race-free.
    const unsigned gbase = g_bar_gen;

    // ---- init h0 / c0 (publish fp16) ----
    float c_reg = 0.f;
    int   my_gu = -1;
    if (tid < nu) {
        my_gu = cta * UPC + tid;
        c_reg = c0[my_gu];
        stcg_u16(&g_h2[0][my_gu], __float2half_rn(h0[my_gu]));
    }

    // ---- Prologue 1: HMMA weight rows -> swizzled fp16 smem (row r = u*4+g) ----
    for (int idx = tid; idx < 4 * uh * 256; idx += NTHREADS) {
        int r = idx >> 8, c = idx & 255;                 // chunk = 16B = 8 halfs
        int u = r >> 2, g = r & 3;
        int grow = g * HDIM + (cta * UPC + u);
        const float4* src = (const float4*)(W_hh + (size_t)grow * HDIM) + c * 2;
        float4 v0 = src[0], v1 = src[1];
        uint4 w;
        __half2* hp = (__half2*)&w;
        hp[0] = __floats2half2_rn(v0.x, v0.y); hp[1] = __floats2half2_rn(v0.z, v0.w);
        hp[2] = __floats2half2_rn(v1.x, v1.y); hp[3] = __floats2half2_rn(v1.z, v1.w);
        *(uint4*)(w_s + r * WSTRIDE + ((c ^ (r & 7)) << 4)) = w;
    }
    // ---- Prologue 2: overflow units (12,13) -> REGISTERS (fp16, resident) ----
    uint4 wreg[2][2];
    #pragma unroll
    for (int j = 0; j < 2; j++) {
        wreg[j][0] = make_uint4(0, 0, 0, 0);
        wreg[j][1] = make_uint4(0, 0, 0, 0);
        if (nu == UPC) {
            int c  = warp * 2 + j;
            int s  = c & 3, rr = c >> 2;
            int u  = 12 + (rr >> 2), g = rr & 3;
            int grow = g * HDIM + (cta * UPC + u);
            const float4* src = (const float4*)(W_hh + (size_t)grow * HDIM + s * 512 + lane * 16);
            float4 v0 = src[0], v1 = src[1], v2 = src[2], v3 = src[3];
            __half2* hp = (__half2*)&wreg[j][0];
            hp[0] = __floats2half2_rn(v0.x, v0.y); hp[1] = __floats2half2_rn(v0.z, v0.w);
            hp[2] = __floats2half2_rn(v1.x, v1.y); hp[3] = __floats2half2_rn(v1.z, v1.w);
            hp = (__half2*)&wreg[j][1];
            hp[0] = __floats2half2_rn(v2.x, v2.y); hp[1] = __floats2half2_rn(v2.z, v2.w);
            hp[2] = __floats2half2_rn(v3.x, v3.y); hp[3] = __floats2half2_rn(v3.z, v3.w);
        }
    }
    // ---- Prologue 3: A = W_ih@W_emb, fused bias ----
    for (int r = warp; r < nrows; r += NWARPS) {
        int u = r >> 2, g = r & 3;
        int grow = g * HDIM + (cta * UPC + u);
        const float* wr = W_ih + (size_t)grow * EDIM;
        float a0 = 0.f, a1 = 0.f, dd = 0.f;
        for (int k = lane; k < EDIM; k += 32) {
            float w = wr[k];
            a0 += w * W_emb[2 * k];
            a1 += w * W_emb[2 * k + 1];
            dd += w * b_emb[k];
        }
        #pragma unroll
        for (int off = 16; off; off >>= 1) {
            a0 += __shfl_xor_sync(0xffffffffu, a0, off);
            a1 += __shfl_xor_sync(0xffffffffu, a1, off);
            dd += __shfl_xor_sync(0xffffffffu, dd, off);
        }
        if (lane == 0) { A0[r] = a0; A1[r] = a1; DD[r] = dd + b_ih[grow] + b_hh[grow]; }
    }
    // ---- Prologue 4: pack W_out fp16 into smem ----
    {
        float4 w0 = *((const float4*)W_out + tid);
        float4 w1 = *((const float4*)(W_out + HDIM) + tid);
        uint4 w;
        __half2* hp = (__half2*)&w;
        hp[0] = __floats2half2_rn(w0.x, w1.x); hp[1] = __floats2half2_rn(w0.y, w1.y);
        hp[2] = __floats2half2_rn(w0.z, w1.z); hp[3] = __floats2half2_rn(w0.w, w1.w);
        wo2_s[tid] = w;
    }
    const float b_o0 = b_out[0], b_o1 = b_out[1];
    float loss = 0.f;
    if (tid == 0) { VW[0] = 1.f; VW[1] = 1.f; }   // x_0 = embedding of ones

    // lane-constant HMMA addressing
    const int warp_t = warp >> 2;
    const int warp_s = warp & 3;
    const int R0 = warp_t * 16;
    const int lrow = R0 + (lane & 15);
    const uint32_t a_rowbase = smem_u32 + OFF_W + (uint32_t)lrow * WSTRIDE;
    const int rx = lrow & 7;
    const int chalf = lane >> 4;
    const uint32_t b_base = smem_u32 + OFF_HS2 + (uint32_t)(warp_s * 1024 + 4 * (lane & 3));
    const uint32_t ch_base0 = smem_u32 + OFF_HS2 + (uint32_t)(((warp * 2)     & 3) * 1024 + lane * 32);
    const uint32_t ch_base1 = smem_u32 + OFF_HS2 + (uint32_t)(((warp * 2 + 1) & 3) * 1024 + lane * 32);

    // ---- Prologue 5: A-fragment register cache (iters 0..ACACHE-1) ----
    __syncthreads();                        // all weight STS visible to ldmatrix
    uint4 acache[ACACHE];
    const bool hmma_on = (warp < 12) && (warp_t * 4 < uh);
    #pragma unroll
    for (int i = 0; i < ACACHE; i++) {
        acache[i] = make_uint4(0, 0, 0, 0);
        if (hmma_on) {
            int c = warp_s * 64 + 2 * i + chalf;
            uint32_t a_addr = a_rowbase + (uint32_t)(((c ^ rx) << 4));
            asm volatile("ldmatrix.sync.aligned.m8n8.x4.shared.b16 {%0,%1,%2,%3}, [%4];"
                         : "=r"(acache[i].x), "=r"(acache[i].y),
                           "=r"(acache[i].z), "=r"(acache[i].w) : "r"(a_addr));
        }
    }
    grid_barrier_exp(lane, gbase + 1u);     // h_0 visible everywhere

    // =============== main recurrence ===============
    for (int t = 0; t < T; t++) {
        // Phase A: load fp16 h_t (4 halfs/thread), stage + W_out partials
        {
            uint2 hv2 = ldcg_u2((const uint2*)&g_h2[t & 1][4 * tid]);
            *(uint2*)(h_s2 + 8 * tid) = hv2;
            float2 h01 = __half22float2(((const __half2*)&hv2)[0]);
            float2 h23 = __half22float2(((const __half2*)&hv2)[1]);
            uint4 w = wo2_s[tid];
            const __half2* hpw = (const __half2*)&w;
            float2 f0 = __half22float2(hpw[0]);
            float2 f1 = __half22float2(hpw[1]);
            float2 f2 = __half22float2(hpw[2]);
            float2 f3 = __half22float2(hpw[3]);
            float p0 = f0.x * h01.x + f1.x * h01.y + f2.x * h23.x + f3.x * h23.y;
            float p1 = f0.y * h01.x + f1.y * h01.y + f2.y * h23.x + f3.y * h23.y;
            wpart[tid] = make_float2(p0, p1);
        }
        __syncthreads();                                   // S2

        // Phase B1: HMMA gates (warps 0-11)
        if (warp < 12) {
            if (hmma_on) {
                float c0a = 0.f, c1a = 0.f, c2a = 0.f, c3a = 0.f;
                float c0b = 0.f, c1b = 0.f, c2b = 0.f, c3b = 0.f;
                // cached-A iterations
                #pragma unroll
                for (int i = 0; i < ACACHE; i++) {
                    uint32_t bb0, bb1;
                    asm volatile("ld.shared.u32 %0, [%1];" : "=r"(bb0) : "r"(b_base + 32u * i));
                    asm volatile("ld.shared.u32 %0, [%1];" : "=r"(bb1) : "r"(b_base + 32u * i + 16u));
                    if (i & 1) {
                        asm volatile(
                            "mma.sync.aligned.m16n8k16.row.col.f32.f16.f16.f32 "
                            "{%0,%1,%2,%3},{%4,%5,%6,%7},{%8,%9},{%0,%1,%2,%3};"
                            : "+f"(c0b), "+f"(c1b), "+f"(c2b), "+f"(c3b)
                            : "r"(acache[i].x), "r"(acache[i].y), "r"(acache[i].z), "r"(acache[i].w),
                              "r"(bb0), "r"(bb1));
                    } else {
                        asm volatile(
                            "mma.sync.aligned.m16n8k16.row.col.f32.f16.f16.f32 "
                            "{%0,%1,%2,%3},{%4,%5,%6,%7},{%8,%9},{%0,%1,%2,%3};"
                            : "+f"(c0a), "+f"(c1a), "+f"(c2a), "+f"(c3a)
                            : "r"(acache[i].x), "r"(acache[i].y), "r"(acache[i].z), "r"(acache[i].w),
                              "r"(bb0), "r"(bb1));
                    }
                }
                // ldmatrix iterations
                #pragma unroll 8
                for (int i = ACACHE; i < 32; i++) {
                    int c = warp_s * 64 + 2 * i + chalf;
                    uint32_t a_addr = a_rowbase + (uint32_t)(((c ^ rx) << 4));
                    uint32_t a0r, a1r, a2r, a3r, bb0, bb1;
                    asm volatile("ldmatrix.sync.aligned.m8n8.x4.shared.b16 {%0,%1,%2,%3}, [%4];"
                                 : "=r"(a0r), "=r"(a1r), "=r"(a2r), "=r"(a3r) : "r"(a_addr));
                    asm volatile("ld.shared.u32 %0, [%1];" : "=r"(bb0) : "r"(b_base + 32u * i));
                    asm volatile("ld.shared.u32 %0, [%1];" : "=r"(bb1) : "r"(b_base + 32u * i + 16u));
                    if (i & 1) {
                        asm volatile(
                            "mma.sync.aligned.m16n8k16.row.col.f32.f16.f16.f32 "
                            "{%0,%1,%2,%3},{%4,%5,%6,%7},{%8,%9},{%0,%1,%2,%3};"
                            : "+f"(c0b), "+f"(c1b), "+f"(c2b), "+f"(c3b)
                            : "r"(a0r), "r"(a1r), "r"(a2r), "r"(a3r), "r"(bb0), "r"(bb1));
                    } else {
                        asm volatile(
                            "mma.sync.aligned.m16n8k16.row.col.f32.f16.f16.f32 "
                            "{%0,%1,%2,%3},{%4,%5,%6,%7},{%8,%9},{%0,%1,%2,%3};"
                            : "+f"(c0a), "+f"(c1a), "+f"(c2a), "+f"(c3a)
                            : "r"(a0r), "r"(a1r), "r"(a2r), "r"(a3r), "r"(bb0), "r"(bb1));
                    }
                }
                float v0 = c0a + c0b, v2 = c2a + c2b;
                if ((lane & 3) == 0) {
                    part[warp_s * PSTRIDE + R0 + (lane >> 2)]     = v0;
                    part[warp_s * PSTRIDE + R0 + (lane >> 2) + 8] = v2;
                }
            }
        } else if (warp == 15) {
            // raw_{t-1} = W_out@h_t + b_out; teacher-forcing select
            float s0 = 0.f, s1 = 0.f;
            const float4* wp4 = (const float4*)wpart;
            #pragma unroll
            for (int i = 0; i < 8; i++) {
                float4 v = wp4[lane * 8 + i];
                s0 += v.x + v.z; s1 += v.y + v.w;
            }
            #pragma unroll
            for (int off = 16; off; off >>= 1) {
                s0 += __shfl_xor_sync(0xffffffffu, s0, off);
                s1 += __shfl_xor_sync(0xffffffffu, s1, off);
            }
            if (lane == 0 && t > 0) {
                float r0 = s0 + b_o0, r1 = s1 + b_o1;
                float gt0 = gtruth[2 * (t - 1)], gt1 = gtruth[2 * (t - 1) + 1];
                int ug = use_gt[t - 1];
                VW[0] = (ug == 1) ? gt0 : r0;
                VW[1] = (ug == 1) ? gt1 : r1;
                if (cta == 0) {
                    out[2 * (t - 1)] = r0; out[2 * (t - 1) + 1] = r1;
                    float d0 = r0 - gt0, d1 = r1 - gt1;
                    loss += 0.5f * (d0 * d0 + d1 * d1);
                }
            }
        }
        // Phase B2: overflow rows 48..55 — 2 register-resident chunks per warp
        if (nu == UPC) {
            #pragma unroll
            for (int j = 0; j < 2; j++) {
                int c = warp * 2 + j;
                uint32_t hb = j ? ch_base1 : ch_base0;
                uint4 hh0, hh1;
                asm volatile("ld.shared.v4.u32 {%0,%1,%2,%3}, [%4];"
                             : "=r"(hh0.x), "=r"(hh0.y), "=r"(hh0.z), "=r"(hh0.w) : "r"(hb));
                asm volatile("ld.shared.v4.u32 {%0,%1,%2,%3}, [%4];"
                             : "=r"(hh1.x), "=r"(hh1.y), "=r"(hh1.z), "=r"(hh1.w) : "r"(hb + 16u));
                float acc = dot16(wreg[j][0], wreg[j][1], hh0, hh1);
                #pragma unroll
                for (int off = 16; off; off >>= 1)
                    acc += __shfl_xor_sync(0xffffffffu, acc, off);
                if (lane == 0) {
                    int s = c & 3, rr = c >> 2;
                    part[s * PSTRIDE + 48 + rr] = acc;
                }
            }
        }
        __syncthreads();                                   // S3

        // Phase C: warp 0 alone: uniform gate epilogue + cell + publish h_{t+1}
        if (warp == 0 && lane < nu) {
            const float v0s = VW[0], v1s = VW[1];
            const float4* p4 = (const float4*)part;        // stride PSTRIDE/4 = 17
            float4 a = p4[0 * 17 + lane];
            float4 b = p4[1 * 17 + lane];
            float4 c = p4[2 * 17 + lane];
            float4 d = p4[3 * 17 + lane];
            float gv0 = (a.x + b.x) + (c.x + d.x);
            float gv1 = (a.y + b.y) + (c.y + d.y);
            float gv2 = (a.z + b.z) + (c.z + d.z);
            float gv3 = (a.w + b.w) + (c.w + d.w);
            int r = 4 * lane;
            gv0 += A0[r]     * v0s + A1[r]     * v1s + DD[r];
            gv1 += A0[r + 1] * v0s + A1[r + 1] * v1s + DD[r + 1];
            gv2 += A0[r + 2] * v0s + A1[r + 2] * v1s + DD[r + 2];
            gv3 += A0[r + 3] * v0s + A1[r + 3] * v1s + DD[r + 3];
            float si = sigf(gv0), sf = sigf(gv1), so = sigf(gv3);
            c_reg = sf * c_reg + si * tanhfast(gv2);
            float hn = so * tanhfast(c_reg);
            stcg_u16(&g_h2[(t + 1) & 1][my_gu], __float2half_rn(hn));
        }
        grid_barrier_exp(lane, gbase + (unsigned)t + 2u);
    }

    // ---- epilogue: raw_{T-1} from h_T, final pred + loss (cta 0 only) ----
    if (cta == 0) {
        {
            uint2 hv2 = ldcg_u2((const uint2*)&g_h2[T & 1][4 * tid]);
            float2 h01 = __half22float2(((const __half2*)&hv2)[0]);
            float2 h23 = __half22float2(((const __half2*)&hv2)[1]);
            uint4 w = wo2_s[tid];
            const __half2* hpw = (const __half2*)&w;
            float2 f0 = __half22float2(hpw[0]);
            float2 f1 = __half22float2(hpw[1]);
            float2 f2 = __half22float2(hpw[2]);
            float2 f3 = __half22float2(hpw[3]);
            float p0 = f0.x * h01.x + f1.x * h01.y + f2.x * h23.x + f3.x * h23.y;
            float p1 = f0.y * h01.x + f1.y * h01.y + f2.y * h23.x + f3.y * h23.y;
            wpart[tid] = make_float2(p0, p1);
        }
        __syncthreads();
        if (warp == 15) {
            float s0 = 0.f, s1 = 0.f;
            const float4* wp4 = (const float4*)wpart;
            #pragma unroll
            for (int i = 0; i < 8; i++) {
                float4 v = wp4[lane * 8 + i];
                s0 += v.x + v.z; s1 += v.y + v.w;
            }
            #pragma unroll
            for (int off = 16; off; off >>= 1) {
                s0 += __shfl_xor_sync(0xffffffffu, s0, off);
                s1 += __shfl_xor_sync(0xffffffffu, s1, off);
            }
            if (lane == 0) {
                float r0 = s0 + b_o0, r1 = s1 + b_o1;
                out[2 * (T - 1)] = r0; out[2 * (T - 1) + 1] = r1;
                float gt0 = gtruth[2 * (T - 1)], gt1 = gtruth[2 * (T - 1) + 1];
                float d0 = r0 - gt0, d1 = r1 - gt1;
                loss += 0.5f * (d0 * d0 + d1 * d1);
                out[2 * T] = loss;
            }
        }
    }
}

// ---------------- launch ----------------
extern "C" void kernel_launch(void* const* d_in, const int* in_sizes, int n_in,
                              void* d_out, int out_size)
{
    (void)in_sizes; (void)out_size;
    const float* h0     = (const float*)d_in[0];
    const float* c0     = (const float*)d_in[1];
    const float* gtruth = (const float*)d_in[2];
    const int*   use_gt = (const int*)  d_in[3];
    const float* W_emb  = (const float*)d_in[4];
    const float* b_emb  = (const float*)d_in[5];
    const float* W_ih   = (const float*)d_in[6];
    const float* b_ih   = (const float*)d_in[7];
    const float* W_hh   = (const float*)d_in[8];
    const float* b_hh   = (const float*)d_in[9];
    const float* W_out  = (const float*)d_in[10];
    const float* b_out  = (const float*)d_in[11];
    const int*   olen   = (n_in > 12) ? (const int*)d_in[12] : nullptr;
    float* out = (float*)d_out;

    cudaFuncSetAttribute(lstm_decoder_kernel,
                         cudaFuncAttributeMaxDynamicSharedMemorySize, SMEM_TOTAL);
    lstm_decoder_kernel<<<NUM_CTAS, NTHREADS, SMEM_TOTAL>>>(
        h0, c0, gtruth, use_gt, W_emb, b_emb, W_ih, b_ih,
        W_hh, b_hh, W_out, b_out, olen, out);
}

// round 16
// speedup vs baseline: 1.3787x; 1.3787x over previous
#include <cuda_runtime.h>
#include <cuda_fp16.h>
#include <cstdint>

// ---------------- problem constants ----------------
#define NUM_CTAS 147
#define NTHREADS 512
#define NWARPS   16
#define HDIM     2048
#define EDIM     1024
#define UPC      14          // units per CTA (146*14 + 4 = 2048)
#define UH       12          // units handled by HMMA (48 rows = 3 m16 tiles)
#define MAXT     2048
#define WSTRIDE  4096        // bytes per smem weight row (2048 fp16)
#define PSTRIDE  68          // part[] strip stride in floats (rows 0..55 used)
#define ACACHE   10          // HMMA iters with register-cached A fragments (R12 optimum)

// smem layout (bytes)
#define OFF_W     0
#define OFF_HS2   (48 * WSTRIDE)             // half h copy (4KB)
#define OFF_WO2   (OFF_HS2 + 4096)           // packed fp16 W_out (8KB)
#define OFF_WPART (OFF_WO2 + 8192)           // per-thread wout partials (4KB)
#define OFF_PART  (OFF_WPART + 4096)         // 4 strips x 68 floats
#define OFF_A0    (OFF_PART + 4 * PSTRIDE * 4)
#define OFF_A1    (OFF_A0 + 256)
#define OFF_DD    (OFF_A1 + 256)
#define OFF_VW    (OFF_DD + 256)
#define SMEM_TOTAL (OFF_VW + 64)

// ---------------- device globals ----------------
__device__ __half    g_h2[2][HDIM];         // double-buffered hidden state (fp16)
__device__ unsigned  g_bar_cnt;             // central barrier (cnt returns to 0)
__device__ unsigned  g_bar_gen;             // monotonically increasing gen

// ---------------- helpers ----------------
__device__ __forceinline__ unsigned ld_acq_u32(const unsigned* p) {
    unsigned v; asm volatile("ld.acquire.gpu.u32 %0, [%1];" : "=r"(v) : "l"(p)); return v;
}
__device__ __forceinline__ void stcg_u16(__half* p, __half v) {
    unsigned short b = __half_as_ushort(v);
    asm volatile("st.global.cg.u16 [%0], %1;" :: "l"(p), "h"(b) : "memory");
}
__device__ __forceinline__ uint2 ldcg_u2(const uint2* p) {
    uint2 v;
    asm volatile("ld.global.cg.v2.u32 {%0,%1}, [%2];"
                 : "=r"(v.x), "=r"(v.y) : "l"(p));
    return v;
}
__device__ __forceinline__ float sigf(float x) { return 1.0f / (1.0f + __expf(-x)); }
__device__ __forceinline__ float tanhfast(float x) {
    return 1.0f - 2.0f / (__expf(2.0f * x) + 1.0f);
}

// dot of 16 fp16 pairs (weights w0:w1, h h0:h1), fp32 accumulate
__device__ __forceinline__ float dot16(uint4 w0, uint4 w1, uint4 h0, uint4 h1) {
    float a0 = 0.f, a1 = 0.f, a2 = 0.f, a3 = 0.f;
    const __half2* wp0 = (const __half2*)&w0;
    const __half2* wp1 = (const __half2*)&w1;
    const __half2* hp0 = (const __half2*)&h0;
    const __half2* hp1 = (const __half2*)&h1;
    #pragma unroll
    for (int i = 0; i < 4; i++) {
        float2 f = __half22float2(wp0[i]);
        float2 g = __half22float2(hp0[i]);
        a0 = fmaf(f.x, g.x, a0); a1 = fmaf(f.y, g.y, a1);
        float2 f2 = __half22float2(wp1[i]);
        float2 g2 = __half22float2(hp1[i]);
        a2 = fmaf(f2.x, g2.x, a2); a3 = fmaf(f2.y, g2.y, a3);
    }
    return (a0 + a1) + (a2 + a3);
}

// central counter barrier (R12-proven: fence + tid0 poll + trailing bar.sync)
__device__ __forceinline__ void grid_barrier() {
    __syncthreads();
    if (threadIdx.x == 0) {
        __threadfence();
        unsigned g = ld_acq_u32(&g_bar_gen);
        if (atomicAdd(&g_bar_cnt, 1u) == NUM_CTAS - 1u) {
            g_bar_cnt = 0u;
            __threadfence();
            atomicAdd(&g_bar_gen, 1u);
        } else {
            while (ld_acq_u32(&g_bar_gen) == g) { }
        }
    }
    __syncthreads();
}

// ---------------- kernel ----------------
__global__ void __launch_bounds__(NTHREADS, 1)
lstm_decoder_kernel(const float* __restrict__ h0, const float* __restrict__ c0,
                    const float* __restrict__ gtruth, const int* __restrict__ use_gt,
                    const float* __restrict__ W_emb, const float* __restrict__ b_emb,
                    const float* __restrict__ W_ih, const float* __restrict__ b_ih,
                    const float* __restrict__ W_hh, const float* __restrict__ b_hh,
                    const float* __restrict__ W_out, const float* __restrict__ b_out,
                    const int* __restrict__ out_len_ptr, float* __restrict__ out)
{
    const int cta  = blockIdx.x;
    const int tid  = threadIdx.x;
    const int lane = tid & 31;
    const int warp = tid >> 5;

    int nu = HDIM - cta * UPC;                 // 14 (ctas 0..145), 4 (cta 146)
    nu = (nu < 0) ? 0 : (nu > UPC ? UPC : nu);
    const int uh = (nu < UH) ? nu : UH;
    const int nrows = 4 * nu;

    int T = MAXT;
    if (out_len_ptr) { int tt = *out_len_ptr; if (tt > 0 && tt <= MAXT) T = tt; }

    extern __shared__ __align__(16) char sm[];
    char*   w_s   = sm + OFF_W;
    char*   h_s2  = sm + OFF_HS2;
    uint4*  wo2_s = (uint4*)(sm + OFF_WO2);
    float2* wpart = (float2*)(sm + OFF_WPART);
    float*  part  = (float*)(sm + OFF_PART);     // [4][PSTRIDE], rows 0..55
    float*  A0    = (float*)(sm + OFF_A0);
    float*  A1    = (float*)(sm + OFF_A1);
    float*  DD    = (float*)(sm + OFF_DD);
    float*  VW    = (float*)(sm + OFF_VW);
    const uint32_t smem_u32 = (uint32_t)__cvta_generic_to_shared(sm);

    // ---- init h0 / c0 (publish fp16) ----
    float c_reg = 0.f;
    int   my_gu = -1;
    if (tid < nu) {
        my_gu = cta * UPC + tid;
        c_reg = c0[my_gu];
        stcg_u16(&g_h2[0][my_gu], __float2half_rn(h0[my_gu]));
    }

    // ---- Prologue 1: HMMA weight rows -> swizzled fp16 smem (row r = u*4+g) ----
    for (int idx = tid; idx < 4 * uh * 256; idx += NTHREADS) {
        int r = idx >> 8, c = idx & 255;                 // chunk = 16B = 8 halfs
        int u = r >> 2, g = r & 3;
        int grow = g * HDIM + (cta * UPC + u);
        const float4* src = (const float4*)(W_hh + (size_t)grow * HDIM) + c * 2;
        float4 v0 = src[0], v1 = src[1];
        uint4 w;
        __half2* hp = (__half2*)&w;
        hp[0] = __floats2half2_rn(v0.x, v0.y); hp[1] = __floats2half2_rn(v0.z, v0.w);
        hp[2] = __floats2half2_rn(v1.x, v1.y); hp[3] = __floats2half2_rn(v1.z, v1.w);
        *(uint4*)(w_s + r * WSTRIDE + ((c ^ (r & 7)) << 4)) = w;
    }
    // ---- Prologue 2: overflow units (12,13) -> REGISTERS (fp16, resident) ----
    uint4 wreg[2][2];
    #pragma unroll
    for (int j = 0; j < 2; j++) {
        wreg[j][0] = make_uint4(0, 0, 0, 0);
        wreg[j][1] = make_uint4(0, 0, 0, 0);
        if (nu == UPC) {
            int c  = warp * 2 + j;
            int s  = c & 3, rr = c >> 2;
            int u  = 12 + (rr >> 2), g = rr & 3;
            int grow = g * HDIM + (cta * UPC + u);
            const float4* src = (const float4*)(W_hh + (size_t)grow * HDIM + s * 512 + lane * 16);
            float4 v0 = src[0], v1 = src[1], v2 = src[2], v3 = src[3];
            __half2* hp = (__half2*)&wreg[j][0];
            hp[0] = __floats2half2_rn(v0.x, v0.y); hp[1] = __floats2half2_rn(v0.z, v0.w);
            hp[2] = __floats2half2_rn(v1.x, v1.y); hp[3] = __floats2half2_rn(v1.z, v1.w);
            hp = (__half2*)&wreg[j][1];
            hp[0] = __floats2half2_rn(v2.x, v2.y); hp[1] = __floats2half2_rn(v2.z, v2.w);
            hp[2] = __floats2half2_rn(v3.x, v3.y); hp[3] = __floats2half2_rn(v3.z, v3.w);
        }
    }
    // ---- Prologue 3: A = W_ih@W_emb, fused bias ----
    for (int r = warp; r < nrows; r += NWARPS) {
        int u = r >> 2, g = r & 3;
        int grow = g * HDIM + (cta * UPC + u);
        const float* wr = W_ih + (size_t)grow * EDIM;
        float a0 = 0.f, a1 = 0.f, dd = 0.f;
        for (int k = lane; k < EDIM; k += 32) {
            float w = wr[k];
            a0 += w * W_emb[2 * k];
            a1 += w * W_emb[2 * k + 1];
            dd += w * b_emb[k];
        }
        #pragma unroll
        for (int off = 16; off; off >>= 1) {
            a0 += __shfl_xor_sync(0xffffffffu, a0, off);
            a1 += __shfl_xor_sync(0xffffffffu, a1, off);
            dd += __shfl_xor_sync(0xffffffffu, dd, off);
        }
        if (lane == 0) { A0[r] = a0; A1[r] = a1; DD[r] = dd + b_ih[grow] + b_hh[grow]; }
    }
    // ---- Prologue 4: pack W_out fp16 into smem ----
    {
        float4 w0 = *((const float4*)W_out + tid);
        float4 w1 = *((const float4*)(W_out + HDIM) + tid);
        uint4 w;
        __half2* hp = (__half2*)&w;
        hp[0] = __floats2half2_rn(w0.x, w1.x); hp[1] = __floats2half2_rn(w0.y, w1.y);
        hp[2] = __floats2half2_rn(w0.z, w1.z); hp[3] = __floats2half2_rn(w0.w, w1.w);
        wo2_s[tid] = w;
    }
    const float b_o0 = b_out[0], b_o1 = b_out[1];
    float loss = 0.f;
    if (tid == 0) { VW[0] = 1.f; VW[1] = 1.f; }   // x_0 = embedding of ones

    // lane-constant HMMA addressing
    const int warp_t = warp >> 2;
    const int warp_s = warp & 3;
    const int R0 = warp_t * 16;
    const int lrow = R0 + (lane & 15);
    const uint32_t a_rowbase = smem_u32 + OFF_W + (uint32_t)lrow * WSTRIDE;
    const int rx = lrow & 7;
    const int chalf = lane >> 4;
    const uint32_t b_base = smem_u32 + OFF_HS2 + (uint32_t)(warp_s * 1024 + 4 * (lane & 3));
    const uint32_t ch_base0 = smem_u32 + OFF_HS2 + (uint32_t)(((warp * 2)     & 3) * 1024 + lane * 32);
    const uint32_t ch_base1 = smem_u32 + OFF_HS2 + (uint32_t)(((warp * 2 + 1) & 3) * 1024 + lane * 32);

    // ---- Prologue 5: A-fragment register cache (iters 0..ACACHE-1) ----
    __syncthreads();                        // all weight STS visible to ldmatrix
    uint4 acache[ACACHE];
    const bool hmma_on = (warp < 12) && (warp_t * 4 < uh);
    #pragma unroll
    for (int i = 0; i < ACACHE; i++) {
        acache[i] = make_uint4(0, 0, 0, 0);
        if (hmma_on) {
            int c = warp_s * 64 + 2 * i + chalf;
            uint32_t a_addr = a_rowbase + (uint32_t)(((c ^ rx) << 4));
            asm volatile("ldmatrix.sync.aligned.m8n8.x4.shared.b16 {%0,%1,%2,%3}, [%4];"
                         : "=r"(acache[i].x), "=r"(acache[i].y),
                           "=r"(acache[i].z), "=r"(acache[i].w) : "r"(a_addr));
        }
    }
    grid_barrier();                         // h_0 visible everywhere

    // =============== main recurrence ===============
    for (int t = 0; t < T; t++) {
        // Phase A: load fp16 h_t (4 halfs/thread), stage + W_out partials
        {
            uint2 hv2 = ldcg_u2((const uint2*)&g_h2[t & 1][4 * tid]);
            *(uint2*)(h_s2 + 8 * tid) = hv2;
            float2 h01 = __half22float2(((const __half2*)&hv2)[0]);
            float2 h23 = __half22float2(((const __half2*)&hv2)[1]);
            uint4 w = wo2_s[tid];
            const __half2* hpw = (const __half2*)&w;
            float2 f0 = __half22float2(hpw[0]);
            float2 f1 = __half22float2(hpw[1]);
            float2 f2 = __half22float2(hpw[2]);
            float2 f3 = __half22float2(hpw[3]);
            float p0 = f0.x * h01.x + f1.x * h01.y + f2.x * h23.x + f3.x * h23.y;
            float p1 = f0.y * h01.x + f1.y * h01.y + f2.y * h23.x + f3.y * h23.y;
            wpart[tid] = make_float2(p0, p1);
        }
        __syncthreads();                                   // S2

        // Phase B1: HMMA gates (warps 0-11)
        if (warp < 12) {
            if (hmma_on) {
                float c0a = 0.f, c1a = 0.f, c2a = 0.f, c3a = 0.f;
                float c0b = 0.f, c1b = 0.f, c2b = 0.f, c3b = 0.f;
                // cached-A iterations
                #pragma unroll
                for (int i = 0; i < ACACHE; i++) {
                    uint32_t bb0, bb1;
                    asm volatile("ld.shared.u32 %0, [%1];" : "=r"(bb0) : "r"(b_base + 32u * i));
                    asm volatile("ld.shared.u32 %0, [%1];" : "=r"(bb1) : "r"(b_base + 32u * i + 16u));
                    if (i & 1) {
                        asm volatile(
                            "mma.sync.aligned.m16n8k16.row.col.f32.f16.f16.f32 "
                            "{%0,%1,%2,%3},{%4,%5,%6,%7},{%8,%9},{%0,%1,%2,%3};"
                            : "+f"(c0b), "+f"(c1b), "+f"(c2b), "+f"(c3b)
                            : "r"(acache[i].x), "r"(acache[i].y), "r"(acache[i].z), "r"(acache[i].w),
                              "r"(bb0), "r"(bb1));
                    } else {
                        asm volatile(
                            "mma.sync.aligned.m16n8k16.row.col.f32.f16.f16.f32 "
                            "{%0,%1,%2,%3},{%4,%5,%6,%7},{%8,%9},{%0,%1,%2,%3};"
                            : "+f"(c0a), "+f"(c1a), "+f"(c2a), "+f"(c3a)
                            : "r"(acache[i].x), "r"(acache[i].y), "r"(acache[i].z), "r"(acache[i].w),
                              "r"(bb0), "r"(bb1));
                    }
                }
                // ldmatrix iterations
                #pragma unroll 8
                for (int i = ACACHE; i < 32; i++) {
                    int c = warp_s * 64 + 2 * i + chalf;
                    uint32_t a_addr = a_rowbase + (uint32_t)(((c ^ rx) << 4));
                    uint32_t a0r, a1r, a2r, a3r, bb0, bb1;
                    asm volatile("ldmatrix.sync.aligned.m8n8.x4.shared.b16 {%0,%1,%2,%3}, [%4];"
                                 : "=r"(a0r), "=r"(a1r), "=r"(a2r), "=r"(a3r) : "r"(a_addr));
                    asm volatile("ld.shared.u32 %0, [%1];" : "=r"(bb0) : "r"(b_base + 32u * i));
                    asm volatile("ld.shared.u32 %0, [%1];" : "=r"(bb1) : "r"(b_base + 32u * i + 16u));
                    if (i & 1) {
                        asm volatile(
                            "mma.sync.aligned.m16n8k16.row.col.f32.f16.f16.f32 "
                            "{%0,%1,%2,%3},{%4,%5,%6,%7},{%8,%9},{%0,%1,%2,%3};"
                            : "+f"(c0b), "+f"(c1b), "+f"(c2b), "+f"(c3b)
                            : "r"(a0r), "r"(a1r), "r"(a2r), "r"(a3r), "r"(bb0), "r"(bb1));
                    } else {
                        asm volatile(
                            "mma.sync.aligned.m16n8k16.row.col.f32.f16.f16.f32 "
                            "{%0,%1,%2,%3},{%4,%5,%6,%7},{%8,%9},{%0,%1,%2,%3};"
                            : "+f"(c0a), "+f"(c1a), "+f"(c2a), "+f"(c3a)
                            : "r"(a0r), "r"(a1r), "r"(a2r), "r"(a3r), "r"(bb0), "r"(bb1));
                    }
                }
                float v0 = c0a + c0b, v2 = c2a + c2b;
                if ((lane & 3) == 0) {
                    part[warp_s * PSTRIDE + R0 + (lane >> 2)]     = v0;
                    part[warp_s * PSTRIDE + R0 + (lane >> 2) + 8] = v2;
                }
            }
        } else if (warp == 15) {
            // raw_{t-1} = W_out@h_t + b_out; conflict-free traversal (i*32+lane)
            float s0 = 0.f, s1 = 0.f;
            const float4* wp4 = (const float4*)wpart;
            #pragma unroll
            for (int i = 0; i < 8; i++) {
                float4 v = wp4[i * 32 + lane];
                s0 += v.x + v.z; s1 += v.y + v.w;
            }
            #pragma unroll
            for (int off = 16; off; off >>= 1) {
                s0 += __shfl_xor_sync(0xffffffffu, s0, off);
                s1 += __shfl_xor_sync(0xffffffffu, s1, off);
            }
            if (lane == 0 && t > 0) {
                float r0 = s0 + b_o0, r1 = s1 + b_o1;
                float gt0 = gtruth[2 * (t - 1)], gt1 = gtruth[2 * (t - 1) + 1];
                int ug = use_gt[t - 1];
                VW[0] = (ug == 1) ? gt0 : r0;
                VW[1] = (ug == 1) ? gt1 : r1;
                if (cta == 0) {
                    out[2 * (t - 1)] = r0; out[2 * (t - 1) + 1] = r1;
                    float d0 = r0 - gt0, d1 = r1 - gt1;
                    loss += 0.5f * (d0 * d0 + d1 * d1);
                }
            }
        }
        // Phase B2: overflow rows 48..55 — 2 register-resident chunks per warp
        if (nu == UPC) {
            #pragma unroll
            for (int j = 0; j < 2; j++) {
                int c = warp * 2 + j;
                uint32_t hb = j ? ch_base1 : ch_base0;
                uint4 hh0, hh1;
                asm volatile("ld.shared.v4.u32 {%0,%1,%2,%3}, [%4];"
                             : "=r"(hh0.x), "=r"(hh0.y), "=r"(hh0.z), "=r"(hh0.w) : "r"(hb));
                asm volatile("ld.shared.v4.u32 {%0,%1,%2,%3}, [%4];"
                             : "=r"(hh1.x), "=r"(hh1.y), "=r"(hh1.z), "=r"(hh1.w) : "r"(hb + 16u));
                float acc = dot16(wreg[j][0], wreg[j][1], hh0, hh1);
                #pragma unroll
                for (int off = 16; off; off >>= 1)
                    acc += __shfl_xor_sync(0xffffffffu, acc, off);
                if (lane == 0) {
                    int s = c & 3, rr = c >> 2;
                    part[s * PSTRIDE + 48 + rr] = acc;
                }
            }
        }
        __syncthreads();                                   // S3

        // Phase C: warp 0 alone: uniform gate epilogue + cell + publish h_{t+1}
        if (warp == 0 && lane < nu) {
            const float v0s = VW[0], v1s = VW[1];
            const float4* p4 = (const float4*)part;        // stride PSTRIDE/4 = 17
            float4 a = p4[0 * 17 + lane];
            float4 b = p4[1 * 17 + lane];
            float4 c = p4[2 * 17 + lane];
            float4 d = p4[3 * 17 + lane];
            float gv0 = (a.x + b.x) + (c.x + d.x);
            float gv1 = (a.y + b.y) + (c.y + d.y);
            float gv2 = (a.z + b.z) + (c.z + d.z);
            float gv3 = (a.w + b.w) + (c.w + d.w);
            int r = 4 * lane;
            gv0 += A0[r]     * v0s + A1[r]     * v1s + DD[r];
            gv1 += A0[r + 1] * v0s + A1[r + 1] * v1s + DD[r + 1];
            gv2 += A0[r + 2] * v0s + A1[r + 2] * v1s + DD[r + 2];
            gv3 += A0[r + 3] * v0s + A1[r + 3] * v1s + DD[r + 3];
            float si = sigf(gv0), sf = sigf(gv1), so = sigf(gv3);
            c_reg = sf * c_reg + si * tanhfast(gv2);
            float hn = so * tanhfast(c_reg);
            stcg_u16(&g_h2[(t + 1) & 1][my_gu], __float2half_rn(hn));
        }
        grid_barrier();   // orders h publish; wakes everyone for t+1
    }

    // ---- epilogue: raw_{T-1} from h_T, final pred + loss (cta 0 only) ----
    if (cta == 0) {
        {
            uint2 hv2 = ldcg_u2((const uint2*)&g_h2[T & 1][4 * tid]);
            float2 h01 = __half22float2(((const __half2*)&hv2)[0]);
            float2 h23 = __half22float2(((const __half2*)&hv2)[1]);
            uint4 w = wo2_s[tid];
            const __half2* hpw = (const __half2*)&w;
            float2 f0 = __half22float2(hpw[0]);
            float2 f1 = __half22float2(hpw[1]);
            float2 f2 = __half22float2(hpw[2]);
            float2 f3 = __half22float2(hpw[3]);
            float p0 = f0.x * h01.x + f1.x * h01.y + f2.x * h23.x + f3.x * h23.y;
            float p1 = f0.y * h01.x + f1.y * h01.y + f2.y * h23.x + f3.y * h23.y;
            wpart[tid] = make_float2(p0, p1);
        }
        __syncthreads();
        if (warp == 15) {
            float s0 = 0.f, s1 = 0.f;
            const float4* wp4 = (const float4*)wpart;
            #pragma unroll
            for (int i = 0; i < 8; i++) {
                float4 v = wp4[i * 32 + lane];
                s0 += v.x + v.z; s1 += v.y + v.w;
            }
            #pragma unroll
            for (int off = 16; off; off >>= 1) {
                s0 += __shfl_xor_sync(0xffffffffu, s0, off);
                s1 += __shfl_xor_sync(0xffffffffu, s1, off);
            }
            if (lane == 0) {
                float r0 = s0 + b_o0, r1 = s1 + b_o1;
                out[2 * (T - 1)] = r0; out[2 * (T - 1) + 1] = r1;
                float gt0 = gtruth[2 * (T - 1)], gt1 = gtruth[2 * (T - 1) + 1];
                float d0 = r0 - gt0, d1 = r1 - gt1;
                loss += 0.5f * (d0 * d0 + d1 * d1);
                out[2 * T] = loss;
            }
        }
    }
}

// ---------------- launch ----------------
extern "C" void kernel_launch(void* const* d_in, const int* in_sizes, int n_in,
                              void* d_out, int out_size)
{
    (void)in_sizes; (void)out_size;
    const float* h0     = (const float*)d_in[0];
    const float* c0     = (const float*)d_in[1];
    const float* gtruth = (const float*)d_in[2];
    const int*   use_gt = (const int*)  d_in[3];
    const float* W_emb  = (const float*)d_in[4];
    const float* b_emb  = (const float*)d_in[5];
    const float* W_ih   = (const float*)d_in[6];
    const float* b_ih   = (const float*)d_in[7];
    const float* W_hh   = (const float*)d_in[8];
    const float* b_hh   = (const float*)d_in[9];
    const float* W_out  = (const float*)d_in[10];
    const float* b_out  = (const float*)d_in[11];
    const int*   olen   = (n_in > 12) ? (const int*)d_in[12] : nullptr;
    float* out = (float*)d_out;

    cudaFuncSetAttribute(lstm_decoder_kernel,
                         cudaFuncAttributeMaxDynamicSharedMemorySize, SMEM_TOTAL);
    lstm_decoder_kernel<<<NUM_CTAS, NTHREADS, SMEM_TOTAL>>>(
        h0, c0, gtruth, use_gt, W_emb, b_emb, W_ih, b_ih,
        W_hh, b_hh, W_out, b_out, olen, out);
}

// round 17
// speedup vs baseline: 1.4022x; 1.0170x over previous
#include <cuda_runtime.h>
#include <cuda_fp16.h>
#include <cstdint>

// ---------------- problem constants ----------------
#define NUM_CTAS 147
#define NTHREADS 512
#define NWARPS   16
#define HDIM     2048
#define EDIM     1024
#define UPC      14          // units per CTA (146*14 + 4 = 2048)
#define UH       12          // units handled by HMMA (48 rows = 3 m16 tiles)
#define MAXT     2048
#define WSTRIDE  4096        // bytes per smem weight row (2048 fp16)
#define PSTRIDE  68          // part[] strip stride in floats (rows 0..55 used)
#define ACACHE   10          // HMMA iters with register-cached A fragments (R12 optimum)

// smem layout (bytes)
#define OFF_W     0
#define OFF_HS2   (48 * WSTRIDE)             // half h copy (4KB)
#define OFF_WO2   (OFF_HS2 + 4096)           // packed fp16 W_out (8KB)
#define OFF_WPART (OFF_WO2 + 8192)           // per-thread wout partials (4KB)
#define OFF_PART  (OFF_WPART + 4096)         // 4 strips x 68 floats
#define OFF_A0    (OFF_PART + 4 * PSTRIDE * 4)
#define OFF_A1    (OFF_A0 + 256)
#define OFF_DD    (OFF_A1 + 256)
#define OFF_VW    (OFF_DD + 256)
#define SMEM_TOTAL (OFF_VW + 64)

// ---------------- device globals ----------------
__device__ __half    g_h2[2][HDIM];         // double-buffered hidden state (fp16)
__device__ unsigned  g_bar_cnt;             // central barrier (cnt returns to 0)
__device__ unsigned  g_bar_gen;             // monotonically increasing gen

// ---------------- helpers ----------------
__device__ __forceinline__ unsigned ld_acq_u32(const unsigned* p) {
    unsigned v; asm volatile("ld.acquire.gpu.u32 %0, [%1];" : "=r"(v) : "l"(p)); return v;
}
__device__ __forceinline__ void stcg_u16(__half* p, __half v) {
    unsigned short b = __half_as_ushort(v);
    asm volatile("st.global.cg.u16 [%0], %1;" :: "l"(p), "h"(b) : "memory");
}
__device__ __forceinline__ uint2 ldcg_u2(const uint2* p) {
    uint2 v;
    asm volatile("ld.global.cg.v2.u32 {%0,%1}, [%2];"
                 : "=r"(v.x), "=r"(v.y) : "l"(p));
    return v;
}
__device__ __forceinline__ float sigf(float x) { return 1.0f / (1.0f + __expf(-x)); }
__device__ __forceinline__ float tanhfast(float x) {
    return 1.0f - 2.0f / (__expf(2.0f * x) + 1.0f);
}

// dot of 16 fp16 pairs (weights w0:w1, h h0:h1), fp32 accumulate
__device__ __forceinline__ float dot16(uint4 w0, uint4 w1, uint4 h0, uint4 h1) {
    float a0 = 0.f, a1 = 0.f, a2 = 0.f, a3 = 0.f;
    const __half2* wp0 = (const __half2*)&w0;
    const __half2* wp1 = (const __half2*)&w1;
    const __half2* hp0 = (const __half2*)&h0;
    const __half2* hp1 = (const __half2*)&h1;
    #pragma unroll
    for (int i = 0; i < 4; i++) {
        float2 f = __half22float2(wp0[i]);
        float2 g = __half22float2(hp0[i]);
        a0 = fmaf(f.x, g.x, a0); a1 = fmaf(f.y, g.y, a1);
        float2 f2 = __half22float2(wp1[i]);
        float2 g2 = __half22float2(hp1[i]);
        a2 = fmaf(f2.x, g2.x, a2); a3 = fmaf(f2.y, g2.y, a3);
    }
    return (a0 + a1) + (a2 + a3);
}

// central counter barrier (R12-proven: fence + tid0 poll + trailing bar.sync)
__device__ __forceinline__ void grid_barrier() {
    __syncthreads();
    if (threadIdx.x == 0) {
        __threadfence();
        unsigned g = ld_acq_u32(&g_bar_gen);
        if (atomicAdd(&g_bar_cnt, 1u) == NUM_CTAS - 1u) {
            g_bar_cnt = 0u;
            __threadfence();
            atomicAdd(&g_bar_gen, 1u);
        } else {
            while (ld_acq_u32(&g_bar_gen) == g) { }
        }
    }
    __syncthreads();
}

// ---------------- kernel ----------------
__global__ void __launch_bounds__(NTHREADS, 1)
lstm_decoder_kernel(const float* __restrict__ h0, const float* __restrict__ c0,
                    const float* __restrict__ gtruth, const int* __restrict__ use_gt,
                    const float* __restrict__ W_emb, const float* __restrict__ b_emb,
                    const float* __restrict__ W_ih, const float* __restrict__ b_ih,
                    const float* __restrict__ W_hh, const float* __restrict__ b_hh,
                    const float* __restrict__ W_out, const float* __restrict__ b_out,
                    const int* __restrict__ out_len_ptr, float* __restrict__ out)
{
    const int cta  = blockIdx.x;
    const int tid  = threadIdx.x;
    const int lane = tid & 31;
    const int warp = tid >> 5;

    int nu = HDIM - cta * UPC;                 // 14 (ctas 0..145), 4 (cta 146)
    nu = (nu < 0) ? 0 : (nu > UPC ? UPC : nu);
    const int uh = (nu < UH) ? nu : UH;
    const int nrows = 4 * nu;

    int T = MAXT;
    if (out_len_ptr) { int tt = *out_len_ptr; if (tt > 0 && tt <= MAXT) T = tt; }

    extern __shared__ __align__(16) char sm[];
    char*   w_s   = sm + OFF_W;
    char*   h_s2  = sm + OFF_HS2;
    uint4*  wo2_s = (uint4*)(sm + OFF_WO2);
    float2* wpart = (float2*)(sm + OFF_WPART);
    float*  part  = (float*)(sm + OFF_PART);     // [4][PSTRIDE], rows 0..55
    float*  A0    = (float*)(sm + OFF_A0);
    float*  A1    = (float*)(sm + OFF_A1);
    float*  DD    = (float*)(sm + OFF_DD);
    float*  VW    = (float*)(sm + OFF_VW);
    const uint32_t smem_u32 = (uint32_t)__cvta_generic_to_shared(sm);

    // ---- init h0 / c0 (publish fp16) ----
    float c_reg = 0.f;
    int   my_gu = -1;
    if (tid < nu) {
        my_gu = cta * UPC + tid;
        c_reg = c0[my_gu];
        stcg_u16(&g_h2[0][my_gu], __float2half_rn(h0[my_gu]));
    }

    // ---- Prologue 1: HMMA weight rows -> swizzled fp16 smem (row r = u*4+g) ----
    for (int idx = tid; idx < 4 * uh * 256; idx += NTHREADS) {
        int r = idx >> 8, c = idx & 255;                 // chunk = 16B = 8 halfs
        int u = r >> 2, g = r & 3;
        int grow = g * HDIM + (cta * UPC + u);
        const float4* src = (const float4*)(W_hh + (size_t)grow * HDIM) + c * 2;
        float4 v0 = src[0], v1 = src[1];
        uint4 w;
        __half2* hp = (__half2*)&w;
        hp[0] = __floats2half2_rn(v0.x, v0.y); hp[1] = __floats2half2_rn(v0.z, v0.w);
        hp[2] = __floats2half2_rn(v1.x, v1.y); hp[3] = __floats2half2_rn(v1.z, v1.w);
        *(uint4*)(w_s + r * WSTRIDE + ((c ^ (r & 7)) << 4)) = w;
    }
    // ---- Prologue 2: overflow units (12,13) -> REGISTERS (fp16, resident) ----
    // chunk c = warp*2+j covers strip s=c&3, row rr=c>>2.
    // Conflict-free mapping: wreg[j][0] = w[k = s*512 + lane*8 .. +7],
    //                        wreg[j][1] = w[k = s*512 + 256 + lane*8 .. +7].
    uint4 wreg[2][2];
    #pragma unroll
    for (int j = 0; j < 2; j++) {
        wreg[j][0] = make_uint4(0, 0, 0, 0);
        wreg[j][1] = make_uint4(0, 0, 0, 0);
        if (nu == UPC) {
            int c  = warp * 2 + j;
            int s  = c & 3, rr = c >> 2;
            int u  = 12 + (rr >> 2), g = rr & 3;
            int grow = g * HDIM + (cta * UPC + u);
            const float* base = W_hh + (size_t)grow * HDIM;
            const float4* srcA = (const float4*)(base + s * 512 + lane * 8);
            float4 a0 = srcA[0], a1 = srcA[1];
            __half2* hp = (__half2*)&wreg[j][0];
            hp[0] = __floats2half2_rn(a0.x, a0.y); hp[1] = __floats2half2_rn(a0.z, a0.w);
            hp[2] = __floats2half2_rn(a1.x, a1.y); hp[3] = __floats2half2_rn(a1.z, a1.w);
            const float4* srcB = (const float4*)(base + s * 512 + 256 + lane * 8);
            float4 b0 = srcB[0], b1 = srcB[1];
            hp = (__half2*)&wreg[j][1];
            hp[0] = __floats2half2_rn(b0.x, b0.y); hp[1] = __floats2half2_rn(b0.z, b0.w);
            hp[2] = __floats2half2_rn(b1.x, b1.y); hp[3] = __floats2half2_rn(b1.z, b1.w);
        }
    }
    // ---- Prologue 3: A = W_ih@W_emb, fused bias ----
    for (int r = warp; r < nrows; r += NWARPS) {
        int u = r >> 2, g = r & 3;
        int grow = g * HDIM + (cta * UPC + u);
        const float* wr = W_ih + (size_t)grow * EDIM;
        float a0 = 0.f, a1 = 0.f, dd = 0.f;
        for (int k = lane; k < EDIM; k += 32) {
            float w = wr[k];
            a0 += w * W_emb[2 * k];
            a1 += w * W_emb[2 * k + 1];
            dd += w * b_emb[k];
        }
        #pragma unroll
        for (int off = 16; off; off >>= 1) {
            a0 += __shfl_xor_sync(0xffffffffu, a0, off);
            a1 += __shfl_xor_sync(0xffffffffu, a1, off);
            dd += __shfl_xor_sync(0xffffffffu, dd, off);
        }
        if (lane == 0) { A0[r] = a0; A1[r] = a1; DD[r] = dd + b_ih[grow] + b_hh[grow]; }
    }
    // ---- Prologue 4: pack W_out fp16 into smem ----
    {
        float4 w0 = *((const float4*)W_out + tid);
        float4 w1 = *((const float4*)(W_out + HDIM) + tid);
        uint4 w;
        __half2* hp = (__half2*)&w;
        hp[0] = __floats2half2_rn(w0.x, w1.x); hp[1] = __floats2half2_rn(w0.y, w1.y);
        hp[2] = __floats2half2_rn(w0.z, w1.z); hp[3] = __floats2half2_rn(w0.w, w1.w);
        wo2_s[tid] = w;
    }
    const float b_o0 = b_out[0], b_o1 = b_out[1];
    float loss = 0.f;
    if (tid == 0) { VW[0] = 1.f; VW[1] = 1.f; }   // x_0 = embedding of ones

    // lane-constant HMMA addressing
    const int warp_t = warp >> 2;
    const int warp_s = warp & 3;
    const int R0 = warp_t * 16;
    const int lrow = R0 + (lane & 15);
    const uint32_t a_rowbase = smem_u32 + OFF_W + (uint32_t)lrow * WSTRIDE;
    const int rx = lrow & 7;
    const int chalf = lane >> 4;
    const uint32_t b_base = smem_u32 + OFF_HS2 + (uint32_t)(warp_s * 1024 + 4 * (lane & 3));
    // conflict-free B2 h addressing (stride-16B across lanes)
    const int s0c = (warp * 2) & 3, s1c = (warp * 2 + 1) & 3;
    const uint32_t ch0a = smem_u32 + OFF_HS2 + (uint32_t)(s0c * 1024 + lane * 16);
    const uint32_t ch1a = smem_u32 + OFF_HS2 + (uint32_t)(s1c * 1024 + lane * 16);

    // ---- Prologue 5: A-fragment register cache (iters 0..ACACHE-1) ----
    __syncthreads();                        // all weight STS visible to ldmatrix
    uint4 acache[ACACHE];
    const bool hmma_on = (warp < 12) && (warp_t * 4 < uh);
    #pragma unroll
    for (int i = 0; i < ACACHE; i++) {
        acache[i] = make_uint4(0, 0, 0, 0);
        if (hmma_on) {
            int c = warp_s * 64 + 2 * i + chalf;
            uint32_t a_addr = a_rowbase + (uint32_t)(((c ^ rx) << 4));
            asm volatile("ldmatrix.sync.aligned.m8n8.x4.shared.b16 {%0,%1,%2,%3}, [%4];"
                         : "=r"(acache[i].x), "=r"(acache[i].y),
                           "=r"(acache[i].z), "=r"(acache[i].w) : "r"(a_addr));
        }
    }
    grid_barrier();                         // h_0 visible everywhere

    // =============== main recurrence ===============
    for (int t = 0; t < T; t++) {
        // Phase A: load fp16 h_t (4 halfs/thread), stage + W_out partials
        {
            uint2 hv2 = ldcg_u2((const uint2*)&g_h2[t & 1][4 * tid]);
            *(uint2*)(h_s2 + 8 * tid) = hv2;
            float2 h01 = __half22float2(((const __half2*)&hv2)[0]);
            float2 h23 = __half22float2(((const __half2*)&hv2)[1]);
            uint4 w = wo2_s[tid];
            const __half2* hpw = (const __half2*)&w;
            float2 f0 = __half22float2(hpw[0]);
            float2 f1 = __half22float2(hpw[1]);
            float2 f2 = __half22float2(hpw[2]);
            float2 f3 = __half22float2(hpw[3]);
            float p0 = f0.x * h01.x + f1.x * h01.y + f2.x * h23.x + f3.x * h23.y;
            float p1 = f0.y * h01.x + f1.y * h01.y + f2.y * h23.x + f3.y * h23.y;
            wpart[tid] = make_float2(p0, p1);
        }
        __syncthreads();                                   // S2

        // Phase B1: HMMA gates (warps 0-11)
        if (warp < 12) {
            if (hmma_on) {
                float c0a = 0.f, c1a = 0.f, c2a = 0.f, c3a = 0.f;
                float c0b = 0.f, c1b = 0.f, c2b = 0.f, c3b = 0.f;
                // cached-A iterations
                #pragma unroll
                for (int i = 0; i < ACACHE; i++) {
                    uint32_t bb0, bb1;
                    asm volatile("ld.shared.u32 %0, [%1];" : "=r"(bb0) : "r"(b_base + 32u * i));
                    asm volatile("ld.shared.u32 %0, [%1];" : "=r"(bb1) : "r"(b_base + 32u * i + 16u));
                    if (i & 1) {
                        asm volatile(
                            "mma.sync.aligned.m16n8k16.row.col.f32.f16.f16.f32 "
                            "{%0,%1,%2,%3},{%4,%5,%6,%7},{%8,%9},{%0,%1,%2,%3};"
                            : "+f"(c0b), "+f"(c1b), "+f"(c2b), "+f"(c3b)
                            : "r"(acache[i].x), "r"(acache[i].y), "r"(acache[i].z), "r"(acache[i].w),
                              "r"(bb0), "r"(bb1));
                    } else {
                        asm volatile(
                            "mma.sync.aligned.m16n8k16.row.col.f32.f16.f16.f32 "
                            "{%0,%1,%2,%3},{%4,%5,%6,%7},{%8,%9},{%0,%1,%2,%3};"
                            : "+f"(c0a), "+f"(c1a), "+f"(c2a), "+f"(c3a)
                            : "r"(acache[i].x), "r"(acache[i].y), "r"(acache[i].z), "r"(acache[i].w),
                              "r"(bb0), "r"(bb1));
                    }
                }
                // ldmatrix iterations
                #pragma unroll 8
                for (int i = ACACHE; i < 32; i++) {
                    int c = warp_s * 64 + 2 * i + chalf;
                    uint32_t a_addr = a_rowbase + (uint32_t)(((c ^ rx) << 4));
                    uint32_t a0r, a1r, a2r, a3r, bb0, bb1;
                    asm volatile("ldmatrix.sync.aligned.m8n8.x4.shared.b16 {%0,%1,%2,%3}, [%4];"
                                 : "=r"(a0r), "=r"(a1r), "=r"(a2r), "=r"(a3r) : "r"(a_addr));
                    asm volatile("ld.shared.u32 %0, [%1];" : "=r"(bb0) : "r"(b_base + 32u * i));
                    asm volatile("ld.shared.u32 %0, [%1];" : "=r"(bb1) : "r"(b_base + 32u * i + 16u));
                    if (i & 1) {
                        asm volatile(
                            "mma.sync.aligned.m16n8k16.row.col.f32.f16.f16.f32 "
                            "{%0,%1,%2,%3},{%4,%5,%6,%7},{%8,%9},{%0,%1,%2,%3};"
                            : "+f"(c0b), "+f"(c1b), "+f"(c2b), "+f"(c3b)
                            : "r"(a0r), "r"(a1r), "r"(a2r), "r"(a3r), "r"(bb0), "r"(bb1));
                    } else {
                        asm volatile(
                            "mma.sync.aligned.m16n8k16.row.col.f32.f16.f16.f32 "
                            "{%0,%1,%2,%3},{%4,%5,%6,%7},{%8,%9},{%0,%1,%2,%3};"
                            : "+f"(c0a), "+f"(c1a), "+f"(c2a), "+f"(c3a)
                            : "r"(a0r), "r"(a1r), "r"(a2r), "r"(a3r), "r"(bb0), "r"(bb1));
                    }
                }
                float v0 = c0a + c0b, v2 = c2a + c2b;
                if ((lane & 3) == 0) {
                    part[warp_s * PSTRIDE + R0 + (lane >> 2)]     = v0;
                    part[warp_s * PSTRIDE + R0 + (lane >> 2) + 8] = v2;
                }
            }
        } else if (warp == 15) {
            // raw_{t-1} = W_out@h_t + b_out; conflict-free traversal (i*32+lane)
            float s0 = 0.f, s1 = 0.f;
            const float4* wp4 = (const float4*)wpart;
            #pragma unroll
            for (int i = 0; i < 8; i++) {
                float4 v = wp4[i * 32 + lane];
                s0 += v.x + v.z; s1 += v.y + v.w;
            }
            #pragma unroll
            for (int off = 16; off; off >>= 1) {
                s0 += __shfl_xor_sync(0xffffffffu, s0, off);
                s1 += __shfl_xor_sync(0xffffffffu, s1, off);
            }
            if (lane == 0 && t > 0) {
                float r0 = s0 + b_o0, r1 = s1 + b_o1;
                float gt0 = gtruth[2 * (t - 1)], gt1 = gtruth[2 * (t - 1) + 1];
                int ug = use_gt[t - 1];
                VW[0] = (ug == 1) ? gt0 : r0;
                VW[1] = (ug == 1) ? gt1 : r1;
                if (cta == 0) {
                    out[2 * (t - 1)] = r0; out[2 * (t - 1) + 1] = r1;
                    float d0 = r0 - gt0, d1 = r1 - gt1;
                    loss += 0.5f * (d0 * d0 + d1 * d1);
                }
            }
        }
        // Phase B2: overflow rows 48..55 — conflict-free stride-16B h loads
        if (nu == UPC) {
            #pragma unroll
            for (int j = 0; j < 2; j++) {
                int c = warp * 2 + j;
                uint32_t hba = j ? ch1a : ch0a;
                uint4 hh0, hh1;
                asm volatile("ld.shared.v4.u32 {%0,%1,%2,%3}, [%4];"
                             : "=r"(hh0.x), "=r"(hh0.y), "=r"(hh0.z), "=r"(hh0.w) : "r"(hba));
                asm volatile("ld.shared.v4.u32 {%0,%1,%2,%3}, [%4];"
                             : "=r"(hh1.x), "=r"(hh1.y), "=r"(hh1.z), "=r"(hh1.w) : "r"(hba + 512u));
                float acc = dot16(wreg[j][0], wreg[j][1], hh0, hh1);
                #pragma unroll
                for (int off = 16; off; off >>= 1)
                    acc += __shfl_xor_sync(0xffffffffu, acc, off);
                if (lane == 0) {
                    int s = c & 3, rr = c >> 2;
                    part[s * PSTRIDE + 48 + rr] = acc;
                }
            }
        }
        __syncthreads();                                   // S3

        // Phase C: warp 0 alone: uniform gate epilogue + cell + publish h_{t+1}
        if (warp == 0 && lane < nu) {
            const float v0s = VW[0], v1s = VW[1];
            const float4* p4 = (const float4*)part;        // stride PSTRIDE/4 = 17
            float4 a = p4[0 * 17 + lane];
            float4 b = p4[1 * 17 + lane];
            float4 c = p4[2 * 17 + lane];
            float4 d = p4[3 * 17 + lane];
            float gv0 = (a.x + b.x) + (c.x + d.x);
            float gv1 = (a.y + b.y) + (c.y + d.y);
            float gv2 = (a.z + b.z) + (c.z + d.z);
            float gv3 = (a.w + b.w) + (c.w + d.w);
            int r = 4 * lane;
            gv0 += A0[r]     * v0s + A1[r]     * v1s + DD[r];
            gv1 += A0[r + 1] * v0s + A1[r + 1] * v1s + DD[r + 1];
            gv2 += A0[r + 2] * v0s + A1[r + 2] * v1s + DD[r + 2];
            gv3 += A0[r + 3] * v0s + A1[r + 3] * v1s + DD[r + 3];
            float si = sigf(gv0), sf = sigf(gv1), so = sigf(gv3);
            c_reg = sf * c_reg + si * tanhfast(gv2);
            float hn = so * tanhfast(c_reg);
            stcg_u16(&g_h2[(t + 1) & 1][my_gu], __float2half_rn(hn));
        }
        grid_barrier();   // orders h publish; wakes everyone for t+1
    }

    // ---- epilogue: raw_{T-1} from h_T, final pred + loss (cta 0 only) ----
    if (cta == 0) {
        {
            uint2 hv2 = ldcg_u2((const uint2*)&g_h2[T & 1][4 * tid]);
            float2 h01 = __half22float2(((const __half2*)&hv2)[0]);
            float2 h23 = __half22float2(((const __half2*)&hv2)[1]);
            uint4 w = wo2_s[tid];
            const __half2* hpw = (const __half2*)&w;
            float2 f0 = __half22float2(hpw[0]);
            float2 f1 = __half22float2(hpw[1]);
            float2 f2 = __half22float2(hpw[2]);
            float2 f3 = __half22float2(hpw[3]);
            float p0 = f0.x * h01.x + f1.x * h01.y + f2.x * h23.x + f3.x * h23.y;
            float p1 = f0.y * h01.x + f1.y * h01.y + f2.y * h23.x + f3.y * h23.y;
            wpart[tid] = make_float2(p0, p1);
        }
        __syncthreads();
        if (warp == 15) {
            float s0 = 0.f, s1 = 0.f;
            const float4* wp4 = (const float4*)wpart;
            #pragma unroll
            for (int i = 0; i < 8; i++) {
                float4 v = wp4[i * 32 + lane];
                s0 += v.x + v.z; s1 += v.y + v.w;
            }
            #pragma unroll
            for (int off = 16; off; off >>= 1) {
                s0 += __shfl_xor_sync(0xffffffffu, s0, off);
                s1 += __shfl_xor_sync(0xffffffffu, s1, off);
            }
            if (lane == 0) {
                float r0 = s0 + b_o0, r1 = s1 + b_o1;
                out[2 * (T - 1)] = r0; out[2 * (T - 1) + 1] = r1;
                float gt0 = gtruth[2 * (T - 1)], gt1 = gtruth[2 * (T - 1) + 1];
                float d0 = r0 - gt0, d1 = r1 - gt1;
                loss += 0.5f * (d0 * d0 + d1 * d1);
                out[2 * T] = loss;
            }
        }
    }
}

// ---------------- launch ----------------
extern "C" void kernel_launch(void* const* d_in, const int* in_sizes, int n_in,
                              void* d_out, int out_size)
{
    (void)in_sizes; (void)out_size;
    const float* h0     = (const float*)d_in[0];
    const float* c0     = (const float*)d_in[1];
    const float* gtruth = (const float*)d_in[2];
    const int*   use_gt = (const int*)  d_in[3];
    const float* W_emb  = (const float*)d_in[4];
    const float* b_emb  = (const float*)d_in[5];
    const float* W_ih   = (const float*)d_in[6];
    const float* b_ih   = (const float*)d_in[7];
    const float* W_hh   = (const float*)d_in[8];
    const float* b_hh   = (const float*)d_in[9];
    const float* W_out  = (const float*)d_in[10];
    const float* b_out  = (const float*)d_in[11];
    const int*   olen   = (n_in > 12) ? (const int*)d_in[12] : nullptr;
    float* out = (float*)d_out;

    cudaFuncSetAttribute(lstm_decoder_kernel,
                         cudaFuncAttributeMaxDynamicSharedMemorySize, SMEM_TOTAL);
    lstm_decoder_kernel<<<NUM_CTAS, NTHREADS, SMEM_TOTAL>>>(
        h0, c0, gtruth, use_gt, W_emb, b_emb, W_ih, b_ih,
        W_hh, b_hh, W_out, b_out, olen, out);
}